// round 9
// baseline (speedup 1.0000x reference)
#include <cuda_runtime.h>

#define N_NODES 50000
#define F       128
#define E_MAX   800000
#define TPB_G   512          // GEMM threads/block
#define GRID_G  148          // persistent blocks (1 per SM)
#define TILE_N  32           // nodes per GEMM tile
#define NT      ((N_NODES + TILE_N - 1) / TILE_N)   // 1563 tiles

// ---- static device scratch (no allocs allowed) ----
__device__ int   g_deg[N_NODES];
__device__ int   g_off[N_NODES + 1];
__device__ int   g_cursor[N_NODES];
__device__ int   g_src_sorted[E_MAX];
__device__ float g_agg[N_NODES * F];

// ---- packed fp32x2 helpers (sm_100+; ptxas never auto-emits FFMA2) ----
#define FMA2(d, a, b) asm("fma.rn.f32x2 %0, %1, %2, %0;" : "+l"(d) : "l"(a), "l"(b))
#define UNPACK2(lo, hi, v) asm("mov.b64 {%0, %1}, %2;" : "=f"(lo), "=f"(hi) : "l"(v))

// ---------------------------------------------------------------------------
// CSR build: zero degrees -> histogram -> prefix scan -> reorder src by dst
// ---------------------------------------------------------------------------
__global__ void zero_deg_kernel() {
    int i = blockIdx.x * blockDim.x + threadIdx.x;
    if (i < N_NODES) g_deg[i] = 0;
}

__global__ void hist_kernel(const int* __restrict__ dst, int E) {
    int e = blockIdx.x * blockDim.x + threadIdx.x;
    if (e < E) atomicAdd(&g_deg[dst[e]], 1);
}

__global__ void __launch_bounds__(1024) scan_kernel() {
    __shared__ int wsum[32];
    __shared__ int carry;
    const int t = threadIdx.x, lane = t & 31, wid = t >> 5;
    if (t == 0) carry = 0;
    __syncthreads();
    for (int base = 0; base < N_NODES; base += 1024) {
        int i = base + t;
        int v = (i < N_NODES) ? g_deg[i] : 0;
        int inc = v;
#pragma unroll
        for (int d = 1; d < 32; d <<= 1) {
            int n = __shfl_up_sync(0xffffffffu, inc, d);
            if (lane >= d) inc += n;
        }
        if (lane == 31) wsum[wid] = inc;
        __syncthreads();
        if (wid == 0) {
            int ws = wsum[lane];
            int wi = ws;
#pragma unroll
            for (int d = 1; d < 32; d <<= 1) {
                int n = __shfl_up_sync(0xffffffffu, wi, d);
                if (lane >= d) wi += n;
            }
            wsum[lane] = wi - ws;
        }
        __syncthreads();
        int excl = carry + wsum[wid] + (inc - v);
        if (i < N_NODES) { g_off[i] = excl; g_cursor[i] = excl; }
        __syncthreads();
        if (t == 1023) carry = excl + v;
        __syncthreads();
    }
    if (t == 0) g_off[N_NODES] = carry;
}

__global__ void reorder_kernel(const int* __restrict__ src,
                               const int* __restrict__ dst, int E) {
    int e = blockIdx.x * blockDim.x + threadIdx.x;
    if (e < E) {
        int d = dst[e];
        int pos = atomicAdd(&g_cursor[d], 1);
        g_src_sorted[pos] = src[e];
    }
}

// ---------------------------------------------------------------------------
// Aggregate: one warp per node, neighbor loop unrolled x8 for MLP.
// ---------------------------------------------------------------------------
__global__ void __launch_bounds__(256)
agg_kernel(const float4* __restrict__ x4) {
    int node = (blockIdx.x * blockDim.x + threadIdx.x) >> 5;
    int lane = threadIdx.x & 31;
    if (node >= N_NODES) return;

    int beg = g_off[node];
    int end = g_off[node + 1];
    float4 acc = make_float4(0.f, 0.f, 0.f, 0.f);

    int i = beg;
    for (; i + 8 <= end; i += 8) {
        int s[8];
#pragma unroll
        for (int u = 0; u < 8; u++) s[u] = g_src_sorted[i + u];
        float4 v[8];
#pragma unroll
        for (int u = 0; u < 8; u++) v[u] = x4[s[u] * 32 + lane];
#pragma unroll
        for (int u = 0; u < 8; u++) {
            acc.x += v[u].x; acc.y += v[u].y;
            acc.z += v[u].z; acc.w += v[u].w;
        }
    }
    for (; i < end; i++) {
        int s = g_src_sorted[i];
        float4 v = x4[s * 32 + lane];
        acc.x += v.x; acc.y += v.y; acc.z += v.z; acc.w += v.w;
    }
    reinterpret_cast<float4*>(g_agg)[node * 32 + lane] = acc;
}

// ---------------------------------------------------------------------------
// Persistent dual GEMM + bias + ReLU. 148 blocks x 512 threads.
// Both weight matrices resident in smem as output-pair float2 for the whole
// kernel. Each warp owns 8 output cols (broadcast weight LDS.128); each lane
// owns one node of the 32-node tile (conflict-free LDS.64 on 131-f2 rows).
// Per warp-kk: 4 LDS.128 + 2 LDS.64 + 8 FFMA2 = 14 issue slots vs 16 fma-cyc.
// Next tile's inputs are prefetched into registers during current compute.
// ---------------------------------------------------------------------------
struct PSmem {
    float2 W2rel [F][64];       // [k][o/2] = {W[2p][k], W[2p+1][k]}   64KB
    float2 W2root[F][64];       //                                     64KB
    float2 A2[TILE_N][131];     // [node][k] = {a,a}; 131%16=3 -> cf   32.75KB
    float2 X2[TILE_N][131];     //                                     32.75KB
};

__global__ void __launch_bounds__(TPB_G, 1)
gemm_relu_kernel(const float* __restrict__ x,
                 const float* __restrict__ Wrel,
                 const float* __restrict__ brel,
                 const float* __restrict__ Wroot,
                 float* __restrict__ out) {
    extern __shared__ char smem_raw[];
    PSmem& sm = *reinterpret_cast<PSmem*>(smem_raw);

    const int t    = threadIdx.x;
    const int og   = t >> 5;     // warp id 0..15 -> output cols og*8..+7
    const int lane = t & 31;     // node slot within tile

    // ---- one-time: stage all weights as output pairs ----
    for (int idx = t; idx < F * F; idx += TPB_G) {
        int o = idx >> 7;        // 0..127
        int k = idx & 127;
        reinterpret_cast<float*>(&sm.W2rel [k][o >> 1])[o & 1] = Wrel [idx];
        reinterpret_cast<float*>(&sm.W2root[k][o >> 1])[o & 1] = Wroot[idx];
    }

    // bias for my 8 output cols
    float4 b0 = *reinterpret_cast<const float4*>(&brel[og * 8]);
    float4 b1 = *reinterpret_cast<const float4*>(&brel[og * 8 + 4]);

    // staging mapping: thread -> (node slot, k-quad)
    const int snode = t >> 4;          // 0..31
    const int skq   = (t & 15) * 8;    // 0,8,...,120

    // prefetch first tile into regs
    int tile = blockIdx.x;
    float4 pa0, pa1, px0, px1;
    {
        int gn = tile * TILE_N + snode;
        if (gn >= N_NODES) gn = N_NODES - 1;
        pa0 = *reinterpret_cast<const float4*>(&g_agg[gn * F + skq]);
        pa1 = *reinterpret_cast<const float4*>(&g_agg[gn * F + skq + 4]);
        px0 = *reinterpret_cast<const float4*>(&x[gn * F + skq]);
        px1 = *reinterpret_cast<const float4*>(&x[gn * F + skq + 4]);
    }

    while (true) {
        __syncthreads();   // prev compute done (input buffers free); weights staged

        // ---- store prefetched inputs, duplicated {v,v} ----
        {
            const float* a0 = reinterpret_cast<const float*>(&pa0);
            const float* a1 = reinterpret_cast<const float*>(&pa1);
            const float* x0 = reinterpret_cast<const float*>(&px0);
            const float* x1 = reinterpret_cast<const float*>(&px1);
#pragma unroll
            for (int c = 0; c < 4; c++) {
                sm.A2[snode][skq + c]     = make_float2(a0[c], a0[c]);
                sm.A2[snode][skq + 4 + c] = make_float2(a1[c], a1[c]);
                sm.X2[snode][skq + c]     = make_float2(x0[c], x0[c]);
                sm.X2[snode][skq + 4 + c] = make_float2(x1[c], x1[c]);
            }
        }

        // ---- prefetch next tile (hidden under compute) ----
        int next = tile + GRID_G;
        bool hasNext = next < NT;
        if (hasNext) {
            int gn = next * TILE_N + snode;
            if (gn >= N_NODES) gn = N_NODES - 1;
            pa0 = *reinterpret_cast<const float4*>(&g_agg[gn * F + skq]);
            pa1 = *reinterpret_cast<const float4*>(&g_agg[gn * F + skq + 4]);
            px0 = *reinterpret_cast<const float4*>(&x[gn * F + skq]);
            px1 = *reinterpret_cast<const float4*>(&x[gn * F + skq + 4]);
        }
        __syncthreads();

        // ---- compute: full k=128, FMA-bound ----
        unsigned long long acc[4] = {0ull, 0ull, 0ull, 0ull};
#pragma unroll 8
        for (int kk = 0; kk < F; kk++) {
            ulonglong2 wrA = *reinterpret_cast<const ulonglong2*>(&sm.W2rel [kk][og * 4]);
            ulonglong2 wrB = *reinterpret_cast<const ulonglong2*>(&sm.W2rel [kk][og * 4 + 2]);
            ulonglong2 woA = *reinterpret_cast<const ulonglong2*>(&sm.W2root[kk][og * 4]);
            ulonglong2 woB = *reinterpret_cast<const ulonglong2*>(&sm.W2root[kk][og * 4 + 2]);
            unsigned long long a2 = *reinterpret_cast<const unsigned long long*>(&sm.A2[lane][kk]);
            unsigned long long x2 = *reinterpret_cast<const unsigned long long*>(&sm.X2[lane][kk]);
            FMA2(acc[0], a2, wrA.x);
            FMA2(acc[1], a2, wrA.y);
            FMA2(acc[2], a2, wrB.x);
            FMA2(acc[3], a2, wrB.y);
            FMA2(acc[0], x2, woA.x);
            FMA2(acc[1], x2, woA.y);
            FMA2(acc[2], x2, woB.x);
            FMA2(acc[3], x2, woB.y);
        }

        // ---- epilogue: bias + relu + store ----
        int node = tile * TILE_N + lane;
        if (node < N_NODES) {
            float r[8];
            UNPACK2(r[0], r[1], acc[0]);
            UNPACK2(r[2], r[3], acc[1]);
            UNPACK2(r[4], r[5], acc[2]);
            UNPACK2(r[6], r[7], acc[3]);
            float4 o0, o1;
            o0.x = fmaxf(r[0] + b0.x, 0.f);
            o0.y = fmaxf(r[1] + b0.y, 0.f);
            o0.z = fmaxf(r[2] + b0.z, 0.f);
            o0.w = fmaxf(r[3] + b0.w, 0.f);
            o1.x = fmaxf(r[4] + b1.x, 0.f);
            o1.y = fmaxf(r[5] + b1.y, 0.f);
            o1.z = fmaxf(r[6] + b1.z, 0.f);
            o1.w = fmaxf(r[7] + b1.w, 0.f);
            *reinterpret_cast<float4*>(&out[node * F + og * 8])     = o0;
            *reinterpret_cast<float4*>(&out[node * F + og * 8 + 4]) = o1;
        }

        if (!hasNext) break;
        tile = next;
    }
}

// ---------------------------------------------------------------------------
extern "C" void kernel_launch(void* const* d_in, const int* in_sizes, int n_in,
                              void* d_out, int out_size) {
    const float* x     = (const float*)d_in[0];
    const int*   ei    = (const int*)d_in[1];     // int32 (JAX x64 disabled)
    const float* Wrel  = (const float*)d_in[2];
    const float* brel  = (const float*)d_in[3];
    const float* Wroot = (const float*)d_in[4];
    float*       out   = (float*)d_out;

    const int E = in_sizes[1] / 2;                // 800000
    const int* src = ei;
    const int* dst = ei + E;

    const int smem_bytes = (int)sizeof(PSmem);    // ~193.5KB
    static bool attr_set = false;
    if (!attr_set) {
        cudaFuncSetAttribute(gemm_relu_kernel,
                             cudaFuncAttributeMaxDynamicSharedMemorySize,
                             smem_bytes);
        attr_set = true;
    }

    // 1) CSR build
    zero_deg_kernel<<<(N_NODES + 255) / 256, 256>>>();
    hist_kernel<<<(E + 255) / 256, 256>>>(dst, E);
    scan_kernel<<<1, 1024>>>();
    reorder_kernel<<<(E + 255) / 256, 256>>>(src, dst, E);

    // 2) aggregate: warp per node
    agg_kernel<<<(N_NODES * 32 + 255) / 256, 256>>>(
        reinterpret_cast<const float4*>(x));

    // 3) persistent weights-resident dual GEMM + bias + relu
    gemm_relu_kernel<<<GRID_G, TPB_G, smem_bytes>>>(
        x, Wrel, brel, Wroot, out);
}

// round 10
// speedup vs baseline: 1.5020x; 1.5020x over previous
#include <cuda_runtime.h>

#define N_NODES 50000
#define F       128
#define E_MAX   800000
#define NPB     64      // nodes per block in GEMM
#define KT      32      // weight k-tile

// ---- static device scratch (no allocs allowed) ----
__device__ int   g_deg[N_NODES];
__device__ int   g_off[N_NODES + 1];
__device__ int   g_cursor[N_NODES];
__device__ int   g_src_sorted[E_MAX];
__device__ float g_agg[N_NODES * F];

// ---- packed fp32x2 helpers (sm_100+; ptxas never auto-emits FFMA2) ----
#define FMA2(d, a, b) asm("fma.rn.f32x2 %0, %1, %2, %0;" : "+l"(d) : "l"(a), "l"(b))
#define PACK2(d, s)   asm("mov.b64 %0, {%1, %1};" : "=l"(d) : "f"(s))
#define UNPACK2(lo, hi, v) asm("mov.b64 {%0, %1}, %2;" : "=f"(lo), "=f"(hi) : "l"(v))

// ---------------------------------------------------------------------------
// CSR build: zero degrees -> histogram -> prefix scan -> reorder src by dst
// ---------------------------------------------------------------------------
__global__ void zero_deg_kernel() {
    int i = blockIdx.x * blockDim.x + threadIdx.x;
    if (i < N_NODES) g_deg[i] = 0;
}

__global__ void hist_kernel(const int* __restrict__ dst, int E) {
    int e = blockIdx.x * blockDim.x + threadIdx.x;
    if (e < E) atomicAdd(&g_deg[dst[e]], 1);
}

// single-block scan, 4 elements per thread (13 barrier iterations)
__global__ void __launch_bounds__(1024) scan_kernel() {
    __shared__ int wsum[32];
    __shared__ int carry;
    const int t = threadIdx.x, lane = t & 31, wid = t >> 5;
    if (t == 0) carry = 0;
    __syncthreads();
    for (int base = 0; base < N_NODES; base += 4096) {
        int i = base + t * 4;
        int v[4], s = 0;
#pragma unroll
        for (int j = 0; j < 4; j++) {
            v[j] = (i + j < N_NODES) ? g_deg[i + j] : 0;
            s += v[j];
        }
        int inc = s;
#pragma unroll
        for (int d = 1; d < 32; d <<= 1) {
            int n = __shfl_up_sync(0xffffffffu, inc, d);
            if (lane >= d) inc += n;
        }
        if (lane == 31) wsum[wid] = inc;
        __syncthreads();
        if (wid == 0) {
            int ws = wsum[lane];
            int wi = ws;
#pragma unroll
            for (int d = 1; d < 32; d <<= 1) {
                int n = __shfl_up_sync(0xffffffffu, wi, d);
                if (lane >= d) wi += n;
            }
            wsum[lane] = wi - ws;
        }
        __syncthreads();
        int run = carry + wsum[wid] + (inc - s);   // exclusive at v[0]
#pragma unroll
        for (int j = 0; j < 4; j++) {
            if (i + j < N_NODES) { g_off[i + j] = run; g_cursor[i + j] = run; }
            run += v[j];
        }
        __syncthreads();           // all reads of carry done
        if (t == 1023) carry = run;
        __syncthreads();
    }
    if (t == 0) g_off[N_NODES] = carry;
}

__global__ void reorder_kernel(const int* __restrict__ src,
                               const int* __restrict__ dst, int E) {
    int e = blockIdx.x * blockDim.x + threadIdx.x;
    if (e < E) {
        int d = dst[e];
        int pos = atomicAdd(&g_cursor[d], 1);
        g_src_sorted[pos] = src[e];
    }
}

// ---------------------------------------------------------------------------
// Aggregate: TWO warps per node (each owns half a row, float2 lanes = 256B
// gathers). 100k warps chip-wide, unroll x8 -> high MLP, half the tail skew.
// ---------------------------------------------------------------------------
__global__ void __launch_bounds__(256)
agg_kernel(const float2* __restrict__ x2) {
    int gw   = (blockIdx.x * blockDim.x + threadIdx.x) >> 5;
    int lane = threadIdx.x & 31;
    if (gw >= 2 * N_NODES) return;
    int node = gw >> 1;
    int col  = (gw & 1) * 32 + lane;    // float2 index within 64-f2 row

    int beg = g_off[node];
    int end = g_off[node + 1];
    float2 acc = make_float2(0.f, 0.f);

    int i = beg;
    for (; i + 8 <= end; i += 8) {
        int s[8];
#pragma unroll
        for (int u = 0; u < 8; u++) s[u] = g_src_sorted[i + u];
        float2 v[8];
#pragma unroll
        for (int u = 0; u < 8; u++) v[u] = x2[s[u] * 64 + col];
#pragma unroll
        for (int u = 0; u < 8; u++) { acc.x += v[u].x; acc.y += v[u].y; }
    }
    for (; i < end; i++) {
        float2 v = x2[g_src_sorted[i] * 64 + col];
        acc.x += v.x; acc.y += v.y;
    }
    reinterpret_cast<float2*>(g_agg)[node * 64 + col] = acc;
}

// ---------------------------------------------------------------------------
// Dual GEMM + bias + ReLU, FFMA2 (output pairs). 256 threads, 64 nodes/block,
// 3 blocks/SM. Thread tile: 8 outputs (og = t>>4, broadcast weight LDS.128)
// x 4 nodes (ng = t&15, padded rows -> conflict-free LDS.32). Next k-tile's
// inputs prefetched into registers during current compute.
// ---------------------------------------------------------------------------
struct GemmSmem {
    float2 sW2rel [KT][64];    // [kk][o/2] = (W[2p][k], W[2p+1][k])  16KB
    float2 sW2root[KT][64];    //                                     16KB
    float  sA[NPB][KT + 1];    // [node][kk]                          8.25KB
    float  sX[NPB][KT + 1];    //                                     8.25KB
};

__global__ void __launch_bounds__(256, 3)
gemm_relu_kernel(const float* __restrict__ x,
                 const float* __restrict__ Wrel,
                 const float* __restrict__ brel,
                 const float* __restrict__ Wroot,
                 float* __restrict__ out) {
    extern __shared__ char smem_raw[];
    GemmSmem& sm = *reinterpret_cast<GemmSmem*>(smem_raw);

    const int t  = threadIdx.x;
    const int og = t >> 4;     // 0..15 -> output cols og*8..+7 (uniform/half-warp)
    const int ng = t & 15;     // nodes ng, ng+16, ng+32, ng+48
    const int nodeBase = blockIdx.x * NPB;

    // staging mapping: thread -> (node slot, k-quad)
    const int slot = t >> 2;          // 0..63
    const int kq   = (t & 3) * 8;     // 0,8,16,24
    int gc;
    {
        int node = nodeBase + slot;
        gc = node < N_NODES ? node : N_NODES - 1;
    }

    // prefetch first tile's inputs
    float4 pa0 = *reinterpret_cast<const float4*>(&g_agg[gc * F + kq]);
    float4 pa1 = *reinterpret_cast<const float4*>(&g_agg[gc * F + kq + 4]);
    float4 px0 = *reinterpret_cast<const float4*>(&x    [gc * F + kq]);
    float4 px1 = *reinterpret_cast<const float4*>(&x    [gc * F + kq + 4]);

    unsigned long long acc[4][4];
#pragma unroll
    for (int n = 0; n < 4; n++)
#pragma unroll
        for (int p = 0; p < 4; p++) acc[n][p] = 0ull;

    for (int kc = 0; kc < F; kc += KT) {
        __syncthreads();

        // --- stage weights as adjacent-output pairs: sW2[kk][o/2]
        {
            int o  = t >> 1;            // 0..127
            int wq = (t & 1) * 16;      // 0 or 16
#pragma unroll
            for (int j = 0; j < 4; j++) {
                float4 wr = *reinterpret_cast<const float4*>(&Wrel [o * F + kc + wq + j * 4]);
                float4 wo = *reinterpret_cast<const float4*>(&Wroot[o * F + kc + wq + j * 4]);
                const float* wrp = reinterpret_cast<const float*>(&wr);
                const float* wop = reinterpret_cast<const float*>(&wo);
#pragma unroll
                for (int c = 0; c < 4; c++) {
                    reinterpret_cast<float*>(&sm.sW2rel [wq + j * 4 + c][o >> 1])[o & 1] = wrp[c];
                    reinterpret_cast<float*>(&sm.sW2root[wq + j * 4 + c][o >> 1])[o & 1] = wop[c];
                }
            }
        }
        // --- store prefetched inputs (scalar stores into padded rows)
        {
            const float* ap0 = reinterpret_cast<const float*>(&pa0);
            const float* ap1 = reinterpret_cast<const float*>(&pa1);
            const float* xp0 = reinterpret_cast<const float*>(&px0);
            const float* xp1 = reinterpret_cast<const float*>(&px1);
#pragma unroll
            for (int c = 0; c < 4; c++) {
                sm.sA[slot][kq + c]     = ap0[c];
                sm.sA[slot][kq + 4 + c] = ap1[c];
                sm.sX[slot][kq + c]     = xp0[c];
                sm.sX[slot][kq + 4 + c] = xp1[c];
            }
        }
        // --- prefetch next tile's inputs (hidden under compute)
        if (kc + KT < F) {
            pa0 = *reinterpret_cast<const float4*>(&g_agg[gc * F + kc + KT + kq]);
            pa1 = *reinterpret_cast<const float4*>(&g_agg[gc * F + kc + KT + kq + 4]);
            px0 = *reinterpret_cast<const float4*>(&x    [gc * F + kc + KT + kq]);
            px1 = *reinterpret_cast<const float4*>(&x    [gc * F + kc + KT + kq + 4]);
        }
        __syncthreads();

        // --- compute: per kk: 4 broadcast LDS.128 + 8 cf LDS.32 + packs + 32 FFMA2
        const int opb = og * 4;
#pragma unroll
        for (int kk = 0; kk < KT; kk++) {
            ulonglong2 wrA = *reinterpret_cast<const ulonglong2*>(&sm.sW2rel [kk][opb]);
            ulonglong2 wrB = *reinterpret_cast<const ulonglong2*>(&sm.sW2rel [kk][opb + 2]);
            ulonglong2 woA = *reinterpret_cast<const ulonglong2*>(&sm.sW2root[kk][opb]);
            ulonglong2 woB = *reinterpret_cast<const ulonglong2*>(&sm.sW2root[kk][opb + 2]);
#pragma unroll
            for (int n = 0; n < 4; n++) {
                float a  = sm.sA[ng + 16 * n][kk];
                float xx = sm.sX[ng + 16 * n][kk];
                unsigned long long a2, x2;
                PACK2(a2, a);
                PACK2(x2, xx);
                FMA2(acc[n][0], a2, wrA.x);
                FMA2(acc[n][1], a2, wrA.y);
                FMA2(acc[n][2], a2, wrB.x);
                FMA2(acc[n][3], a2, wrB.y);
                FMA2(acc[n][0], x2, woA.x);
                FMA2(acc[n][1], x2, woA.y);
                FMA2(acc[n][2], x2, woB.x);
                FMA2(acc[n][3], x2, woB.y);
            }
        }
    }

    // ---- epilogue: bias + relu + store ----
    float4 b0 = *reinterpret_cast<const float4*>(&brel[og * 8]);
    float4 b1 = *reinterpret_cast<const float4*>(&brel[og * 8 + 4]);
#pragma unroll
    for (int n = 0; n < 4; n++) {
        int node = nodeBase + ng + 16 * n;
        if (node < N_NODES) {
            float r[8];
            UNPACK2(r[0], r[1], acc[n][0]);
            UNPACK2(r[2], r[3], acc[n][1]);
            UNPACK2(r[4], r[5], acc[n][2]);
            UNPACK2(r[6], r[7], acc[n][3]);
            float4 o0, o1;
            o0.x = fmaxf(r[0] + b0.x, 0.f);
            o0.y = fmaxf(r[1] + b0.y, 0.f);
            o0.z = fmaxf(r[2] + b0.z, 0.f);
            o0.w = fmaxf(r[3] + b0.w, 0.f);
            o1.x = fmaxf(r[4] + b1.x, 0.f);
            o1.y = fmaxf(r[5] + b1.y, 0.f);
            o1.z = fmaxf(r[6] + b1.z, 0.f);
            o1.w = fmaxf(r[7] + b1.w, 0.f);
            float4* orow = reinterpret_cast<float4*>(out) + node * 32;
            orow[og * 2]     = o0;
            orow[og * 2 + 1] = o1;
        }
    }
}

// ---------------------------------------------------------------------------
extern "C" void kernel_launch(void* const* d_in, const int* in_sizes, int n_in,
                              void* d_out, int out_size) {
    const float* x     = (const float*)d_in[0];
    const int*   ei    = (const int*)d_in[1];     // int32 (JAX x64 disabled)
    const float* Wrel  = (const float*)d_in[2];
    const float* brel  = (const float*)d_in[3];
    const float* Wroot = (const float*)d_in[4];
    float*       out   = (float*)d_out;

    const int E = in_sizes[1] / 2;                // 800000
    const int* src = ei;
    const int* dst = ei + E;

    const int smem_bytes = (int)sizeof(GemmSmem);     // ~48.5KB
    static bool attr_set = false;
    if (!attr_set) {
        cudaFuncSetAttribute(gemm_relu_kernel,
                             cudaFuncAttributeMaxDynamicSharedMemorySize,
                             smem_bytes);
        attr_set = true;
    }

    // 1) CSR build
    zero_deg_kernel<<<(N_NODES + 255) / 256, 256>>>();
    hist_kernel<<<(E + 255) / 256, 256>>>(dst, E);
    scan_kernel<<<1, 1024>>>();
    reorder_kernel<<<(E + 255) / 256, 256>>>(src, dst, E);

    // 2) aggregate: 2 warps per node (half-row each)
    agg_kernel<<<(2 * N_NODES * 32 + 255) / 256, 256>>>(
        reinterpret_cast<const float2*>(x));

    // 3) dual GEMM + bias + relu
    gemm_relu_kernel<<<(N_NODES + NPB - 1) / NPB, 256, smem_bytes>>>(
        x, Wrel, brel, Wroot, out);
}